// round 9
// baseline (speedup 1.0000x reference)
#include <cuda_runtime.h>
#include <cuda_fp16.h>

#define Bq 512
#define Tq 128
#define Eq 256
#define Dq 256
#define G4 1024
#define BT (Bq*Tq)
#define NBLK 512
#define NLEAF 16
#define PER_LEAF 32   // 512 = 16*32

// ---------------- static device scratch ----------------
__device__ __half g_pre[(size_t)BT * Eq];     // enc @ W1_enc + b1 (fp16, 32MB) — immutable in persist
__device__ float g_encfc[BT];                 // enc[b,t,:] . fc_w[0:256] — immutable
__device__ float g_whhT[Dq * G4];             // w_hh transposed — immutable
__device__ float g_bsum[G4];
__device__ float g_h[Bq * Dq];                // mutable
__device__ float g_c[Bq * Dq];                // mutable
__device__ float g_hp[16 * Bq * Eq];          // 16 K-partials of [h|c]@W1_hc
__device__ float g_gp[8 * (size_t)Bq * G4];   // 8 K-partials of h@w_hhT
__device__ unsigned g_cnt[NLEAF * 32];
__device__ unsigned g_master;
__device__ volatile unsigned g_gen;

struct SmA { float As[16][136]; float Bs[16][68]; };
struct SmB {
    float hp[256]; float sc[128]; float ctxp[8][256];
    float ctx[256]; float red[8]; float misc[4];
};
union Smem { SmA a; SmB b; };

__device__ __forceinline__ float tanh_approx(float x) {
    float y; asm("tanh.approx.f32 %0, %1;" : "=f"(y) : "f"(x)); return y;
}
__device__ __forceinline__ float sigmoid_f(float x) {
    return __fdividef(1.0f, 1.0f + __expf(-x));
}

// 128x64 output tile, K multiple of 16, 256 threads, 8x4 microtile.
// A mutable -> __ldcg; B immutable weights -> __ldg.
template<typename TO>
__device__ __forceinline__ void gemm128x64(SmA* s,
        const float* __restrict__ A, int lda,
        const float* __restrict__ Bm, int ldb,
        TO* __restrict__ C, int ldc, int K,
        const float* __restrict__ bias)
{
    const int tid = threadIdx.x;
    const int ty = tid >> 4, tx = tid & 15;
    const int arow = tid >> 2, ac4 = (tid & 3) << 2;
    const int bk = tid >> 4, bc4 = (tid & 15) << 2;

    float acc[8][4];
#pragma unroll
    for (int i = 0; i < 8; i++)
#pragma unroll
        for (int j = 0; j < 4; j++) acc[i][j] = 0.f;

    for (int k0 = 0; k0 < K; k0 += 16) {
        float4 av0 = __ldcg((const float4*)(A + (size_t)arow * lda + k0 + ac4));
        float4 av1 = __ldcg((const float4*)(A + (size_t)(arow + 64) * lda + k0 + ac4));
        float4 bv  = __ldg((const float4*)(Bm + (size_t)(k0 + bk) * ldb + bc4));
        s->As[ac4 + 0][arow] = av0.x; s->As[ac4 + 1][arow] = av0.y;
        s->As[ac4 + 2][arow] = av0.z; s->As[ac4 + 3][arow] = av0.w;
        s->As[ac4 + 0][arow + 64] = av1.x; s->As[ac4 + 1][arow + 64] = av1.y;
        s->As[ac4 + 2][arow + 64] = av1.z; s->As[ac4 + 3][arow + 64] = av1.w;
        *(float4*)&s->Bs[bk][bc4] = bv;
        __syncthreads();
#pragma unroll
        for (int k = 0; k < 16; k++) {
            float4 a0 = *(const float4*)&s->As[k][ty << 3];
            float4 a1 = *(const float4*)&s->As[k][(ty << 3) + 4];
            float4 b4 = *(const float4*)&s->Bs[k][tx << 2];
            float av[8] = {a0.x, a0.y, a0.z, a0.w, a1.x, a1.y, a1.z, a1.w};
            float bb[4] = {b4.x, b4.y, b4.z, b4.w};
#pragma unroll
            for (int i = 0; i < 8; i++)
#pragma unroll
                for (int j = 0; j < 4; j++)
                    acc[i][j] = fmaf(av[i], bb[j], acc[i][j]);
        }
        __syncthreads();
    }
#pragma unroll
    for (int i = 0; i < 8; i++) {
        float v0 = acc[i][0], v1 = acc[i][1], v2 = acc[i][2], v3 = acc[i][3];
        if (bias) {
            v0 += bias[(tx << 2) + 0]; v1 += bias[(tx << 2) + 1];
            v2 += bias[(tx << 2) + 2]; v3 += bias[(tx << 2) + 3];
        }
        size_t off = (size_t)((ty << 3) + i) * ldc + (tx << 2);
        if constexpr (sizeof(TO) == 2) {
            __half2 h0 = __floats2half2_rn(v0, v1);
            __half2 h1 = __floats2half2_rn(v2, v3);
            uint2 u; u.x = *(unsigned*)&h0; u.y = *(unsigned*)&h1;
            *(uint2*)((__half*)C + off) = u;
        } else {
            *(float4*)((float*)C + off) = make_float4(v0, v1, v2, v3);
        }
    }
}

__device__ __forceinline__ void gridbar() {
    __threadfence();
    __syncthreads();
    if (threadIdx.x == 0) {
        unsigned gen = g_gen;
        unsigned leaf = (blockIdx.x & (NLEAF - 1)) * 32;
        unsigned v = atomicAdd(&g_cnt[leaf], 1u) + 1u;
        if (v == (gen + 1u) * PER_LEAF) {
            unsigned m = atomicAdd(&g_master, 1u) + 1u;
            if (m == (gen + 1u) * NLEAF) {
                __threadfence();
                g_gen = gen + 1u;
            } else {
                while (g_gen == gen) __nanosleep(32);
            }
        } else {
            while (g_gen == gen) __nanosleep(64);
        }
        __threadfence();
    }
    __syncthreads();
}

__global__ void __launch_bounds__(256, 4) decoder_persist(
        const float* __restrict__ enc, const float* __restrict__ yhist,
        const float* __restrict__ attn_w1, const float* __restrict__ attn_w2,
        const float* __restrict__ w_ih,
        const float* __restrict__ fc_w, const float* __restrict__ fc_b,
        const float* __restrict__ fcf_w, const float* __restrict__ fcf_b,
        float* __restrict__ out)
{
    __shared__ Smem sm;
    const int bid = blockIdx.x;
    const int tid = threadIdx.x;
    const int lane = tid & 31, warp = tid >> 5;
    const int b = bid;
    // hp carrier: (bid>>2)&1 alternates across the ~148-stride bid->SM map,
    // so every SM hosts an even mix of 1-unit and 2-unit blocks.
    const bool hp_carrier = (((bid >> 2) & 1) == 0);
    const int hp_u = (bid >> 3) * 4 + (bid & 3);   // in [0,256) over carriers

    for (int t = 0; t < Tq; t++) {
        // ============ phase 1: uniform GEMM units ============
        {   // gp unit (all blocks): h @ w_hhT, 128x64xK32, 8 partials
            int kq = bid & 7, tile = bid >> 3;       // 64 tiles: 4 mt x 16 nt
            int mt = tile >> 4, nt = tile & 15;
            gemm128x64<float>(&sm.a,
                g_h + (size_t)mt * 128 * Dq + kq * 32, Dq,
                g_whhT + (size_t)(kq * 32) * G4 + nt * 64, G4,
                g_gp + (size_t)kq * (Bq * G4) + (size_t)mt * 128 * G4 + nt * 64, G4,
                32, (const float*)0);
        }
        if (hp_carrier) {   // hp unit: [h|c] @ W1_hc, 128x64xK32, 16 partials
            int tile = hp_u >> 4, kq = hp_u & 15;
            int mt = tile >> 2, nt = tile & 3;
            const float* A = (kq < 8 ? g_h + kq * 32 : g_c + (kq - 8) * 32)
                             + (size_t)mt * 128 * Dq;
            gemm128x64<float>(&sm.a, A, Dq,
                attn_w1 + (size_t)(kq * 32) * Eq + nt * 64, Eq,
                g_hp + (size_t)kq * (Bq * Eq) + (size_t)mt * 128 * Eq + nt * 64, Eq,
                32, (const float*)0);
        }
        gridbar();

        // ============ phase 2: attention + LSTM, all row-local (row b = bid) ============
        {
            float hpv = 0.f;
#pragma unroll
            for (int q = 0; q < 16; q++)
                hpv += __ldcg(&g_hp[(size_t)q * (Bq * Eq) + b * Eq + tid]);
            sm.b.hp[tid] = hpv;
            __syncthreads();

            float hpr[8], w2r[8];
#pragma unroll
            for (int j = 0; j < 8; j++) {
                hpr[j] = sm.b.hp[lane * 8 + j];
                w2r[j] = __ldg(&attn_w2[lane * 8 + j]);
            }

            // scores: 8 warps x 16 t's, 4 loads in flight
            const uint4* preb = (const uint4*)(g_pre + (size_t)b * Tq * Eq);
#pragma unroll
            for (int tb = 0; tb < 4; tb++) {
                int tt0 = warp + tb * 32;
                uint4 pv[4];
#pragma unroll
                for (int j = 0; j < 4; j++)
                    pv[j] = __ldg(preb + (size_t)(tt0 + j * 8) * 32 + lane);
#pragma unroll
                for (int j = 0; j < 4; j++) {
                    const __half2* ph = (const __half2*)&pv[j];
                    float a = 0.f;
#pragma unroll
                    for (int q = 0; q < 4; q++) {
                        float2 f = __half22float2(ph[q]);
                        a = fmaf(w2r[2 * q],     tanh_approx(hpr[2 * q]     + f.x), a);
                        a = fmaf(w2r[2 * q + 1], tanh_approx(hpr[2 * q + 1] + f.y), a);
                    }
#pragma unroll
                    for (int o = 16; o; o >>= 1) a += __shfl_xor_sync(0xffffffffu, a, o);
                    if (lane == 0) sm.b.sc[tt0 + j * 8] = a;
                }
            }
            __syncthreads();

            // softmax over T=128 (attn_b2 dropped: shift-invariant)
            float sv = (tid < Tq) ? sm.b.sc[tid] : -3.0e38f;
            float m = sv;
#pragma unroll
            for (int o = 16; o; o >>= 1) m = fmaxf(m, __shfl_xor_sync(0xffffffffu, m, o));
            if (lane == 0) sm.b.red[warp] = m;
            __syncthreads();
            if (tid == 0) {
                float mm = sm.b.red[0];
#pragma unroll
                for (int w = 1; w < 8; w++) mm = fmaxf(mm, sm.b.red[w]);
                sm.b.misc[0] = mm;
            }
            __syncthreads();
            float ex = (tid < Tq) ? __expf(sv - sm.b.misc[0]) : 0.f;
            float ss = ex;
#pragma unroll
            for (int o = 16; o; o >>= 1) ss += __shfl_xor_sync(0xffffffffu, ss, o);
            if (lane == 0) sm.b.red[warp] = ss;
            __syncthreads();
            if (tid == 0) {
                float tot = 0.f;
#pragma unroll
                for (int w = 0; w < 8; w++) tot += sm.b.red[w];
                sm.b.misc[1] = __fdividef(1.0f, tot);
            }
            if (tid < Tq) sm.b.sc[tid] = ex;
            __syncthreads();
            float invs = sm.b.misc[1];

            // y_dot = sum_t ex[t] * encfc[b,t]
            float yd = (tid < Tq) ? sm.b.sc[tid] * __ldg(&g_encfc[b * Tq + tid]) : 0.f;
#pragma unroll
            for (int o = 16; o; o >>= 1) yd += __shfl_xor_sync(0xffffffffu, yd, o);
            if (lane == 0) sm.b.red[warp] = yd;
            __syncthreads();
            if (tid == 0) {
                float tot = 0.f;
#pragma unroll
                for (int w = 0; w < 8; w++) tot += sm.b.red[w];
                sm.b.misc[2] = tot * invs + __ldg(&yhist[b * Tq + t]) * fc_w[256] + fc_b[0];
            }

            // full ctx only at the final step (for fc_final)
            if (t == Tq - 1) {
                float a8[8] = {0.f, 0.f, 0.f, 0.f, 0.f, 0.f, 0.f, 0.f};
                const float4* encb = (const float4*)(enc + (size_t)b * Tq * Eq);
#pragma unroll 2
                for (int i = 0; i < 16; i++) {
                    int tt = (warp << 4) + i;
                    float wgt = sm.b.sc[tt];
                    float4 e0 = __ldg(encb + (size_t)tt * 64 + lane * 2);
                    float4 e1 = __ldg(encb + (size_t)tt * 64 + lane * 2 + 1);
                    a8[0] = fmaf(wgt, e0.x, a8[0]); a8[1] = fmaf(wgt, e0.y, a8[1]);
                    a8[2] = fmaf(wgt, e0.z, a8[2]); a8[3] = fmaf(wgt, e0.w, a8[3]);
                    a8[4] = fmaf(wgt, e1.x, a8[4]); a8[5] = fmaf(wgt, e1.y, a8[5]);
                    a8[6] = fmaf(wgt, e1.z, a8[6]); a8[7] = fmaf(wgt, e1.w, a8[7]);
                }
#pragma unroll
                for (int j = 0; j < 8; j++) sm.b.ctxp[warp][lane * 8 + j] = a8[j];
                __syncthreads();
                float cv = 0.f;
#pragma unroll
                for (int w = 0; w < 8; w++) cv += sm.b.ctxp[w][tid];
                sm.b.ctx[tid] = cv * invs;
            }
            __syncthreads();

            // LSTM epilogue (thread = d)
            float yt = sm.b.misc[2];
            int d = tid;
            float gv[4];
#pragma unroll
            for (int g = 0; g < 4; g++) {
                float a = fmaf(yt, __ldg(&w_ih[g * 256 + d]), g_bsum[g * 256 + d]);
#pragma unroll
                for (int kq = 0; kq < 8; kq++)
                    a += __ldcg(&g_gp[(size_t)kq * (Bq * G4) + (size_t)b * G4 + g * 256 + d]);
                gv[g] = a;
            }
            float cprev = __ldcg(&g_c[b * Dq + d]);
            float cn = sigmoid_f(gv[1]) * cprev + sigmoid_f(gv[0]) * tanhf(gv[2]);
            float hn = sigmoid_f(gv[3]) * tanhf(cn);
            g_c[b * Dq + d] = cn;
            g_h[b * Dq + d] = hn;

            if (t == Tq - 1) {
                float q = hn * __ldg(&fcf_w[d]) + sm.b.ctx[d] * __ldg(&fcf_w[Dq + d]);
#pragma unroll
                for (int o = 16; o; o >>= 1) q += __shfl_xor_sync(0xffffffffu, q, o);
                __syncthreads();
                if (lane == 0) sm.b.red[warp] = q;
                __syncthreads();
                if (tid == 0) {
                    float tot = 0.f;
#pragma unroll
                    for (int w = 0; w < 8; w++) tot += sm.b.red[w];
                    out[b] = tot + fcf_b[0];
                }
            }
        }
        gridbar();
    }
}

__global__ void prep_kernel(const float* __restrict__ w_hh,
                            const float* __restrict__ b_ih,
                            const float* __restrict__ b_hh)
{
    int i = blockIdx.x * blockDim.x + threadIdx.x;
    if (i < G4 * Dq) {
        int j = i >> 8, k = i & 255;
        g_whhT[(size_t)k * G4 + j] = w_hh[i];
    }
    if (i < G4) g_bsum[i] = b_ih[i] + b_hh[i];
    if (i < Bq * Dq) { g_h[i] = 0.f; g_c[i] = 0.f; }
    if (i < NLEAF * 32) g_cnt[i] = 0u;
    if (i == 0) { g_master = 0u; g_gen = 0u; }
}

// encfc[b,t] = enc[b,t,:] . fc_w[0:256]   (one warp per (b,t))
__global__ void __launch_bounds__(256) encfc_kernel(
        const float* __restrict__ enc, const float* __restrict__ fc_w)
{
    int w = blockIdx.x * 8 + (threadIdx.x >> 5);
    int lane = threadIdx.x & 31;
    const float4* p = (const float4*)(enc + (size_t)w * Eq);
    const float4* q = (const float4*)fc_w;
    float s = 0.f;
#pragma unroll
    for (int j = 0; j < 2; j++) {
        float4 e = __ldcg(p + lane + 32 * j);
        float4 f = __ldg(q + lane + 32 * j);
        s += e.x * f.x + e.y * f.y + e.z * f.z + e.w * f.w;
    }
#pragma unroll
    for (int o = 16; o; o >>= 1) s += __shfl_xor_sync(0xffffffffu, s, o);
    if (lane == 0) g_encfc[w] = s;
}

__global__ void __launch_bounds__(256) pre_gemm_kernel(
        const float* __restrict__ enc, const float* __restrict__ attn_w1,
        const float* __restrict__ attn_b1)
{
    __shared__ SmA sa;
    int mt = blockIdx.x >> 2, nt = blockIdx.x & 3;
    gemm128x64<__half>(&sa,
        enc + (size_t)mt * 128 * Eq, Eq,
        attn_w1 + (size_t)(2 * Dq) * Eq + nt * 64, Eq,
        g_pre + (size_t)mt * 128 * Eq + nt * 64, Eq, 256,
        attn_b1 + nt * 64);
}

extern "C" void kernel_launch(void* const* d_in, const int* in_sizes, int n_in,
                              void* d_out, int out_size)
{
    const float* enc     = (const float*)d_in[0];
    const float* yhist   = (const float*)d_in[1];
    const float* attn_w1 = (const float*)d_in[2];
    const float* attn_b1 = (const float*)d_in[3];
    const float* attn_w2 = (const float*)d_in[4];
    // d_in[5] = attn_b2: unused (softmax is shift-invariant)
    const float* w_ih    = (const float*)d_in[6];
    const float* w_hh    = (const float*)d_in[7];
    const float* b_ih    = (const float*)d_in[8];
    const float* b_hh    = (const float*)d_in[9];
    const float* fc_w    = (const float*)d_in[10];
    const float* fc_b    = (const float*)d_in[11];
    const float* fcf_w   = (const float*)d_in[12];
    const float* fcf_b   = (const float*)d_in[13];
    float* out = (float*)d_out;

    prep_kernel<<<1024, 256>>>(w_hh, b_ih, b_hh);
    encfc_kernel<<<BT / 8, 256>>>(enc, fc_w);
    pre_gemm_kernel<<<2048, 256>>>(enc, attn_w1, attn_b1);
    decoder_persist<<<NBLK, 256>>>(enc, yhist, attn_w1, attn_w2, w_ih,
                                   fc_w, fc_b, fcf_w, fcf_b, out);
}

// round 10
// speedup vs baseline: 1.1313x; 1.1313x over previous
#include <cuda_runtime.h>
#include <cuda_fp16.h>

#define Bq 512
#define Tq 128
#define Eq 256
#define Dq 256
#define G4 1024
#define BT (Bq*Tq)
#define NBLK 512
#define NLEAF 16
#define PER_LEAF 32   // 512 = 16*32

// ---------------- static device scratch ----------------
__device__ __half g_pre[(size_t)BT * Eq];     // enc @ W1_enc + b1 (fp16, 32MB)
__device__ float g_encfc[BT];                 // enc[b,t,:] . fc_w[0:256]
__device__ float g_whhT[Dq * G4];             // w_hh transposed [k][gate*256+d]
__device__ float g_bsum[G4];
__device__ float g_h[Bq * Dq];
__device__ float g_c[Bq * Dq];
__device__ float g_hp[16 * Bq * Eq];          // 16 K-partials of [h|c]@W1_hc
__device__ float g_gp[4 * (size_t)Bq * G4];   // 4 K-partials of h@w_hhT
__device__ unsigned g_cnt[NLEAF * 32];
__device__ unsigned g_master;
__device__ volatile unsigned g_gen;

struct SmA { float As[16][136]; float Bs[16][68]; };
struct SmB {
    float hp[256]; unsigned hp2[128]; float sc[128]; float ctxp[8][256];
    float ctx[256]; float red[8]; float misc[4];
};
union Smem { SmA a; SmB b; };

__device__ __forceinline__ unsigned tanh_h2(unsigned x) {
    unsigned y; asm("tanh.approx.f16x2 %0, %1;" : "=r"(y) : "r"(x)); return y;
}
__device__ __forceinline__ float sigmoid_f(float x) {
    return __fdividef(1.0f, 1.0f + __expf(-x));
}

// 128x64 output tile, K multiple of 16, 256 threads, 8x4 microtile. (R6 engine)
// A mutable -> __ldcg; B immutable -> __ldg.
template<typename TO>
__device__ __forceinline__ void gemm128x64(SmA* s,
        const float* __restrict__ A, int lda,
        const float* __restrict__ Bm, int ldb,
        TO* __restrict__ C, int ldc, int K,
        const float* __restrict__ bias)
{
    const int tid = threadIdx.x;
    const int ty = tid >> 4, tx = tid & 15;
    const int arow = tid >> 2, ac4 = (tid & 3) << 2;
    const int bk = tid >> 4, bc4 = (tid & 15) << 2;

    float acc[8][4];
#pragma unroll
    for (int i = 0; i < 8; i++)
#pragma unroll
        for (int j = 0; j < 4; j++) acc[i][j] = 0.f;

    for (int k0 = 0; k0 < K; k0 += 16) {
        float4 av0 = __ldcg((const float4*)(A + (size_t)arow * lda + k0 + ac4));
        float4 av1 = __ldcg((const float4*)(A + (size_t)(arow + 64) * lda + k0 + ac4));
        float4 bv  = __ldg((const float4*)(Bm + (size_t)(k0 + bk) * ldb + bc4));
        s->As[ac4 + 0][arow] = av0.x; s->As[ac4 + 1][arow] = av0.y;
        s->As[ac4 + 2][arow] = av0.z; s->As[ac4 + 3][arow] = av0.w;
        s->As[ac4 + 0][arow + 64] = av1.x; s->As[ac4 + 1][arow + 64] = av1.y;
        s->As[ac4 + 2][arow + 64] = av1.z; s->As[ac4 + 3][arow + 64] = av1.w;
        *(float4*)&s->Bs[bk][bc4] = bv;
        __syncthreads();
#pragma unroll
        for (int k = 0; k < 16; k++) {
            float4 a0 = *(const float4*)&s->As[k][ty << 3];
            float4 a1 = *(const float4*)&s->As[k][(ty << 3) + 4];
            float4 b4 = *(const float4*)&s->Bs[k][tx << 2];
            float av[8] = {a0.x, a0.y, a0.z, a0.w, a1.x, a1.y, a1.z, a1.w};
            float bb[4] = {b4.x, b4.y, b4.z, b4.w};
#pragma unroll
            for (int i = 0; i < 8; i++)
#pragma unroll
                for (int j = 0; j < 4; j++)
                    acc[i][j] = fmaf(av[i], bb[j], acc[i][j]);
        }
        __syncthreads();
    }
#pragma unroll
    for (int i = 0; i < 8; i++) {
        float v0 = acc[i][0], v1 = acc[i][1], v2 = acc[i][2], v3 = acc[i][3];
        if (bias) {
            v0 += bias[(tx << 2) + 0]; v1 += bias[(tx << 2) + 1];
            v2 += bias[(tx << 2) + 2]; v3 += bias[(tx << 2) + 3];
        }
        size_t off = (size_t)((ty << 3) + i) * ldc + (tx << 2);
        if constexpr (sizeof(TO) == 2) {
            __half2 h0 = __floats2half2_rn(v0, v1);
            __half2 h1 = __floats2half2_rn(v2, v3);
            uint2 u; u.x = *(unsigned*)&h0; u.y = *(unsigned*)&h1;
            *(uint2*)((__half*)C + off) = u;
        } else {
            *(float4*)((float*)C + off) = make_float4(v0, v1, v2, v3);
        }
    }
}

__device__ __forceinline__ void gridbar() {
    __threadfence();
    __syncthreads();
    if (threadIdx.x == 0) {
        unsigned gen = g_gen;
        unsigned leaf = (blockIdx.x & (NLEAF - 1)) * 32;
        unsigned v = atomicAdd(&g_cnt[leaf], 1u) + 1u;
        if (v == (gen + 1u) * PER_LEAF) {
            unsigned m = atomicAdd(&g_master, 1u) + 1u;
            if (m == (gen + 1u) * NLEAF) {
                __threadfence();
                g_gen = gen + 1u;
            } else {
                while (g_gen == gen) __nanosleep(32);
            }
        } else {
            while (g_gen == gen) __nanosleep(64);
        }
        __threadfence();
    }
    __syncthreads();
}

__global__ void __launch_bounds__(256, 4) decoder_persist(
        const float* __restrict__ enc, const float* __restrict__ yhist,
        const float* __restrict__ attn_w1, const float* __restrict__ attn_w2,
        const float* __restrict__ w_ih,
        const float* __restrict__ fc_w, const float* __restrict__ fc_b,
        const float* __restrict__ fcf_w, const float* __restrict__ fcf_b,
        float* __restrict__ out)
{
    __shared__ Smem sm;
    const int bid = blockIdx.x;
    const int tid = threadIdx.x;
    const int lane = tid & 31, warp = tid >> 5;
    const int b = bid;

    for (int t = 0; t < Tq; t++) {
        // ============ phase 1: step-GEMM partials, one unit per block (R6) ============
        if (bid < 256) {
            // gp unit: h @ w_hhT, tile 128x64, K-chunk 64 -> 4 partials
            int kq = bid & 3, tile = bid >> 2;
            int mt = tile >> 4, nt = tile & 15;
            gemm128x64<float>(&sm.a,
                g_h + (size_t)mt * 128 * Dq + kq * 64, Dq,
                g_whhT + (size_t)(kq * 64) * G4 + nt * 64, G4,
                g_gp + (size_t)kq * (Bq * G4) + (size_t)mt * 128 * G4 + nt * 64, G4,
                64, (const float*)0);
        } else {
            // hp unit: [h|c] @ W1_hc, tile 128x64, K-chunk 32 -> 16 partials
            int u = bid - 256;
            int tile = u >> 4, kq = u & 15;
            int mt = tile >> 2, nt = tile & 3;
            const float* A = (kq < 8 ? g_h + kq * 32 : g_c + (kq - 8) * 32)
                             + (size_t)mt * 128 * Dq;
            gemm128x64<float>(&sm.a, A, Dq,
                attn_w1 + (size_t)(kq * 32) * Eq + nt * 64, Eq,
                g_hp + (size_t)kq * (Bq * Eq) + (size_t)mt * 128 * Eq + nt * 64, Eq,
                32, (const float*)0);
        }
        gridbar();

        // ============ phase 2: attention + LSTM, row-local (row b = bid) ============
        {
            float hpv = 0.f;
#pragma unroll
            for (int q = 0; q < 16; q++)
                hpv += __ldcg(&g_hp[(size_t)q * (Bq * Eq) + b * Eq + tid]);
            sm.b.hp[tid] = hpv;
            __syncthreads();
            if (tid < 128) {
                __half2 h2 = __floats2half2_rn(sm.b.hp[2 * tid], sm.b.hp[2 * tid + 1]);
                sm.b.hp2[tid] = *(unsigned*)&h2;
            }
            __syncthreads();

            unsigned hp2r[4];
            float w2r[8];
#pragma unroll
            for (int q = 0; q < 4; q++) hp2r[q] = sm.b.hp2[lane * 4 + q];
#pragma unroll
            for (int j = 0; j < 8; j++) w2r[j] = __ldg(&attn_w2[lane * 8 + j]);

            // scores: 8 warps x 16 t's, 4 loads in flight; tanh in f16x2 (half MUFU)
            const uint4* preb = (const uint4*)(g_pre + (size_t)b * Tq * Eq);
#pragma unroll
            for (int tb = 0; tb < 4; tb++) {
                int tt0 = warp + tb * 32;
                uint4 pv[4];
#pragma unroll
                for (int j = 0; j < 4; j++)
                    pv[j] = __ldg(preb + (size_t)(tt0 + j * 8) * 32 + lane);
#pragma unroll
                for (int j = 0; j < 4; j++) {
                    const unsigned* ph = (const unsigned*)&pv[j];
                    float a = 0.f;
#pragma unroll
                    for (int q = 0; q < 4; q++) {
                        __half2 x = *(const __half2*)&ph[q] + *(const __half2*)&hp2r[q];
                        unsigned th = tanh_h2(*(unsigned*)&x);
                        float2 f = __half22float2(*(const __half2*)&th);
                        a = fmaf(w2r[2 * q], f.x, a);
                        a = fmaf(w2r[2 * q + 1], f.y, a);
                    }
#pragma unroll
                    for (int o = 16; o; o >>= 1) a += __shfl_xor_sync(0xffffffffu, a, o);
                    if (lane == 0) sm.b.sc[tt0 + j * 8] = a;
                }
            }
            __syncthreads();

            // softmax over T=128 (attn_b2 dropped: shift-invariant)
            float sv = (tid < Tq) ? sm.b.sc[tid] : -3.0e38f;
            float m = sv;
#pragma unroll
            for (int o = 16; o; o >>= 1) m = fmaxf(m, __shfl_xor_sync(0xffffffffu, m, o));
            if (lane == 0) sm.b.red[warp] = m;
            __syncthreads();
            if (tid == 0) {
                float mm = sm.b.red[0];
#pragma unroll
                for (int w = 1; w < 8; w++) mm = fmaxf(mm, sm.b.red[w]);
                sm.b.misc[0] = mm;
            }
            __syncthreads();
            float ex = (tid < Tq) ? __expf(sv - sm.b.misc[0]) : 0.f;
            float ss = ex;
#pragma unroll
            for (int o = 16; o; o >>= 1) ss += __shfl_xor_sync(0xffffffffu, ss, o);
            if (lane == 0) sm.b.red[warp] = ss;
            __syncthreads();
            if (tid == 0) {
                float tot = 0.f;
#pragma unroll
                for (int w = 0; w < 8; w++) tot += sm.b.red[w];
                sm.b.misc[1] = __fdividef(1.0f, tot);
            }
            if (tid < Tq) sm.b.sc[tid] = ex;
            __syncthreads();
            float invs = sm.b.misc[1];

            // y_dot = sum_t ex[t] * encfc[b,t]
            float yd = (tid < Tq) ? sm.b.sc[tid] * __ldg(&g_encfc[b * Tq + tid]) : 0.f;
#pragma unroll
            for (int o = 16; o; o >>= 1) yd += __shfl_xor_sync(0xffffffffu, yd, o);
            if (lane == 0) sm.b.red[warp] = yd;
            __syncthreads();
            if (tid == 0) {
                float tot = 0.f;
#pragma unroll
                for (int w = 0; w < 8; w++) tot += sm.b.red[w];
                sm.b.misc[2] = tot * invs + __ldg(&yhist[b * Tq + t]) * fc_w[256] + fc_b[0];
            }

            // full ctx only at the final step (for fc_final)
            if (t == Tq - 1) {
                float a8[8] = {0.f, 0.f, 0.f, 0.f, 0.f, 0.f, 0.f, 0.f};
                const float4* encb = (const float4*)(enc + (size_t)b * Tq * Eq);
#pragma unroll 2
                for (int i = 0; i < 16; i++) {
                    int tt = (warp << 4) + i;
                    float wgt = sm.b.sc[tt];
                    float4 e0 = __ldg(encb + (size_t)tt * 64 + lane * 2);
                    float4 e1 = __ldg(encb + (size_t)tt * 64 + lane * 2 + 1);
                    a8[0] = fmaf(wgt, e0.x, a8[0]); a8[1] = fmaf(wgt, e0.y, a8[1]);
                    a8[2] = fmaf(wgt, e0.z, a8[2]); a8[3] = fmaf(wgt, e0.w, a8[3]);
                    a8[4] = fmaf(wgt, e1.x, a8[4]); a8[5] = fmaf(wgt, e1.y, a8[5]);
                    a8[6] = fmaf(wgt, e1.z, a8[6]); a8[7] = fmaf(wgt, e1.w, a8[7]);
                }
#pragma unroll
                for (int j = 0; j < 8; j++) sm.b.ctxp[warp][lane * 8 + j] = a8[j];
                __syncthreads();
                float cv = 0.f;
#pragma unroll
                for (int w = 0; w < 8; w++) cv += sm.b.ctxp[w][tid];
                sm.b.ctx[tid] = cv * invs;
            }
            __syncthreads();

            // LSTM epilogue (thread = d)
            float yt = sm.b.misc[2];
            int d = tid;
            float gv[4];
#pragma unroll
            for (int g = 0; g < 4; g++) {
                float a = fmaf(yt, __ldg(&w_ih[g * 256 + d]), g_bsum[g * 256 + d]);
#pragma unroll
                for (int kq = 0; kq < 4; kq++)
                    a += __ldcg(&g_gp[(size_t)kq * (Bq * G4) + (size_t)b * G4 + g * 256 + d]);
                gv[g] = a;
            }
            float cprev = __ldcg(&g_c[b * Dq + d]);
            float cn = sigmoid_f(gv[1]) * cprev + sigmoid_f(gv[0]) * tanhf(gv[2]);
            float hn = sigmoid_f(gv[3]) * tanhf(cn);
            g_c[b * Dq + d] = cn;
            g_h[b * Dq + d] = hn;

            if (t == Tq - 1) {
                float q = hn * __ldg(&fcf_w[d]) + sm.b.ctx[d] * __ldg(&fcf_w[Dq + d]);
#pragma unroll
                for (int o = 16; o; o >>= 1) q += __shfl_xor_sync(0xffffffffu, q, o);
                __syncthreads();
                if (lane == 0) sm.b.red[warp] = q;
                __syncthreads();
                if (tid == 0) {
                    float tot = 0.f;
#pragma unroll
                    for (int w = 0; w < 8; w++) tot += sm.b.red[w];
                    out[b] = tot + fcf_b[0];
                }
            }
        }
        gridbar();
    }
}

__global__ void prep_kernel(const float* __restrict__ w_hh,
                            const float* __restrict__ b_ih,
                            const float* __restrict__ b_hh)
{
    int i = blockIdx.x * blockDim.x + threadIdx.x;
    if (i < G4 * Dq) {
        int j = i >> 8, k = i & 255;
        g_whhT[(size_t)k * G4 + j] = w_hh[i];
    }
    if (i < G4) g_bsum[i] = b_ih[i] + b_hh[i];
    if (i < Bq * Dq) { g_h[i] = 0.f; g_c[i] = 0.f; }
    if (i < NLEAF * 32) g_cnt[i] = 0u;
    if (i == 0) { g_master = 0u; g_gen = 0u; }
}

// encfc[b,t] = enc[b,t,:] . fc_w[0:256]   (one warp per (b,t))
__global__ void __launch_bounds__(256) encfc_kernel(
        const float* __restrict__ enc, const float* __restrict__ fc_w)
{
    int w = blockIdx.x * 8 + (threadIdx.x >> 5);
    int lane = threadIdx.x & 31;
    const float4* p = (const float4*)(enc + (size_t)w * Eq);
    const float4* q = (const float4*)fc_w;
    float s = 0.f;
#pragma unroll
    for (int j = 0; j < 2; j++) {
        float4 e = __ldcg(p + lane + 32 * j);
        float4 f = __ldg(q + lane + 32 * j);
        s += e.x * f.x + e.y * f.y + e.z * f.z + e.w * f.w;
    }
#pragma unroll
    for (int o = 16; o; o >>= 1) s += __shfl_xor_sync(0xffffffffu, s, o);
    if (lane == 0) g_encfc[w] = s;
}

__global__ void __launch_bounds__(256) pre_gemm_kernel(
        const float* __restrict__ enc, const float* __restrict__ attn_w1,
        const float* __restrict__ attn_b1)
{
    __shared__ SmA sa;
    int mt = blockIdx.x >> 2, nt = blockIdx.x & 3;
    gemm128x64<__half>(&sa,
        enc + (size_t)mt * 128 * Eq, Eq,
        attn_w1 + (size_t)(2 * Dq) * Eq + nt * 64, Eq,
        g_pre + (size_t)mt * 128 * Eq + nt * 64, Eq, 256,
        attn_b1 + nt * 64);
}

extern "C" void kernel_launch(void* const* d_in, const int* in_sizes, int n_in,
                              void* d_out, int out_size)
{
    const float* enc     = (const float*)d_in[0];
    const float* yhist   = (const float*)d_in[1];
    const float* attn_w1 = (const float*)d_in[2];
    const float* attn_b1 = (const float*)d_in[3];
    const float* attn_w2 = (const float*)d_in[4];
    // d_in[5] = attn_b2: unused (softmax is shift-invariant)
    const float* w_ih    = (const float*)d_in[6];
    const float* w_hh    = (const float*)d_in[7];
    const float* b_ih    = (const float*)d_in[8];
    const float* b_hh    = (const float*)d_in[9];
    const float* fc_w    = (const float*)d_in[10];
    const float* fc_b    = (const float*)d_in[11];
    const float* fcf_w   = (const float*)d_in[12];
    const float* fcf_b   = (const float*)d_in[13];
    float* out = (float*)d_out;

    prep_kernel<<<1024, 256>>>(w_hh, b_ih, b_hh);
    encfc_kernel<<<BT / 8, 256>>>(enc, fc_w);
    pre_gemm_kernel<<<2048, 256>>>(enc, attn_w1, attn_b1);
    decoder_persist<<<NBLK, 256>>>(enc, yhist, attn_w1, attn_w2, w_ih,
                                   fc_w, fc_b, fcf_w, fcf_b, out);
}

// round 11
// speedup vs baseline: 1.1754x; 1.0390x over previous
#include <cuda_runtime.h>
#include <cuda_fp16.h>

#define Bq 512
#define Tq 128
#define Eq 256
#define Dq 256
#define G4 1024
#define BT (Bq*Tq)
#define NBLK 512
#define NLEAF 16
#define PER_LEAF 32   // 512 = 16*32

// ---------------- static device scratch ----------------
__device__ __half g_pre[(size_t)BT * Eq];     // enc @ W1_enc + b1 (fp16, 32MB)
__device__ float g_encfc[BT];                 // enc[b,t,:] . fc_w[0:256]
__device__ float g_whhT[Dq * G4];             // w_hh transposed [k][gate*256+d]
__device__ float g_bsum[G4];
__device__ float g_h[Bq * Dq];
__device__ float g_c[Bq * Dq];
__device__ float g_hp[16 * Bq * Eq];          // 16 K-partials of [h|c]@W1_hc
__device__ float g_gp[4 * (size_t)Bq * G4];   // 4 K-partials of h@w_hhT
__device__ unsigned g_cnt[NLEAF * 32];
__device__ unsigned g_master;
__device__ volatile unsigned g_gen;

struct SmA { float As[16][136]; float Bs[16][68]; };
struct SmB {
    float hp[256]; unsigned hp2[128]; float sc[128]; float ctxp[8][256];
    float ctx[256]; float red[8]; float misc[4];
};
union Smem { SmA a; SmB b; };

__device__ __forceinline__ unsigned tanh_h2(unsigned x) {
    unsigned y; asm("tanh.approx.f16x2 %0, %1;" : "=r"(y) : "r"(x)); return y;
}
__device__ __forceinline__ float sigmoid_f(float x) {
    return __fdividef(1.0f, 1.0f + __expf(-x));
}

// packed dual-fp32 FMA (Blackwell f32x2 pipe; 2 MACs per issue slot)
#define FMA_X2(acc, a, b) \
    asm("fma.rn.f32x2 %0, %1, %2, %0;" : "+l"(acc) : "l"(a), "l"(b))

__device__ __forceinline__ unsigned long long pack2(float lo, float hi) {
    unsigned long long r;
    asm("mov.b64 %0, {%1, %2};" : "=l"(r) : "f"(lo), "f"(hi));
    return r;
}
__device__ __forceinline__ float2 unpack2(unsigned long long v) {
    float lo, hi;
    asm("mov.b64 {%0, %1}, %2;" : "=f"(lo), "=f"(hi) : "l"(v));
    return make_float2(lo, hi);
}

// 128x64 output tile, K multiple of 16, 256 threads, 8x4 microtile.
// Inner product in packed f32x2 (rows paired) -> 2x fp32 FMA throughput.
// A mutable -> __ldcg; B immutable -> __ldg.
template<typename TO>
__device__ __forceinline__ void gemm128x64(SmA* s,
        const float* __restrict__ A, int lda,
        const float* __restrict__ Bm, int ldb,
        TO* __restrict__ C, int ldc, int K,
        const float* __restrict__ bias)
{
    const int tid = threadIdx.x;
    const int ty = tid >> 4, tx = tid & 15;
    const int arow = tid >> 2, ac4 = (tid & 3) << 2;
    const int bk = tid >> 4, bc4 = (tid & 15) << 2;

    unsigned long long acc2[4][4];   // [row-pair p][col j]: rows (2p,2p+1)
#pragma unroll
    for (int p = 0; p < 4; p++)
#pragma unroll
        for (int j = 0; j < 4; j++) acc2[p][j] = 0ull;

    for (int k0 = 0; k0 < K; k0 += 16) {
        float4 av0 = __ldcg((const float4*)(A + (size_t)arow * lda + k0 + ac4));
        float4 av1 = __ldcg((const float4*)(A + (size_t)(arow + 64) * lda + k0 + ac4));
        float4 bv  = __ldg((const float4*)(Bm + (size_t)(k0 + bk) * ldb + bc4));
        s->As[ac4 + 0][arow] = av0.x; s->As[ac4 + 1][arow] = av0.y;
        s->As[ac4 + 2][arow] = av0.z; s->As[ac4 + 3][arow] = av0.w;
        s->As[ac4 + 0][arow + 64] = av1.x; s->As[ac4 + 1][arow + 64] = av1.y;
        s->As[ac4 + 2][arow + 64] = av1.z; s->As[ac4 + 3][arow + 64] = av1.w;
        *(float4*)&s->Bs[bk][bc4] = bv;
        __syncthreads();
#pragma unroll
        for (int k = 0; k < 16; k++) {
            const float2* ap = (const float2*)&s->As[k][ty << 3];
            float4 b4 = *(const float4*)&s->Bs[k][tx << 2];
            unsigned long long bd0 = pack2(b4.x, b4.x);
            unsigned long long bd1 = pack2(b4.y, b4.y);
            unsigned long long bd2 = pack2(b4.z, b4.z);
            unsigned long long bd3 = pack2(b4.w, b4.w);
#pragma unroll
            for (int p = 0; p < 4; p++) {
                float2 a2 = ap[p];
                unsigned long long av = pack2(a2.x, a2.y);
                FMA_X2(acc2[p][0], av, bd0);
                FMA_X2(acc2[p][1], av, bd1);
                FMA_X2(acc2[p][2], av, bd2);
                FMA_X2(acc2[p][3], av, bd3);
            }
        }
        __syncthreads();
    }
#pragma unroll
    for (int p = 0; p < 4; p++) {
        float2 v0 = unpack2(acc2[p][0]);
        float2 v1 = unpack2(acc2[p][1]);
        float2 v2 = unpack2(acc2[p][2]);
        float2 v3 = unpack2(acc2[p][3]);
        float r0[4] = {v0.x, v1.x, v2.x, v3.x};   // row 2p
        float r1[4] = {v0.y, v1.y, v2.y, v3.y};   // row 2p+1
        if (bias) {
#pragma unroll
            for (int j = 0; j < 4; j++) {
                float bj = bias[(tx << 2) + j];
                r0[j] += bj; r1[j] += bj;
            }
        }
        size_t off0 = (size_t)((ty << 3) + 2 * p) * ldc + (tx << 2);
        size_t off1 = off0 + ldc;
        if constexpr (sizeof(TO) == 2) {
            __half2 h00 = __floats2half2_rn(r0[0], r0[1]);
            __half2 h01 = __floats2half2_rn(r0[2], r0[3]);
            __half2 h10 = __floats2half2_rn(r1[0], r1[1]);
            __half2 h11 = __floats2half2_rn(r1[2], r1[3]);
            uint2 u0; u0.x = *(unsigned*)&h00; u0.y = *(unsigned*)&h01;
            uint2 u1; u1.x = *(unsigned*)&h10; u1.y = *(unsigned*)&h11;
            *(uint2*)((__half*)C + off0) = u0;
            *(uint2*)((__half*)C + off1) = u1;
        } else {
            *(float4*)((float*)C + off0) = make_float4(r0[0], r0[1], r0[2], r0[3]);
            *(float4*)((float*)C + off1) = make_float4(r1[0], r1[1], r1[2], r1[3]);
        }
    }
}

__device__ __forceinline__ void gridbar() {
    __threadfence();
    __syncthreads();
    if (threadIdx.x == 0) {
        unsigned gen = g_gen;
        unsigned leaf = (blockIdx.x & (NLEAF - 1)) * 32;
        unsigned v = atomicAdd(&g_cnt[leaf], 1u) + 1u;
        if (v == (gen + 1u) * PER_LEAF) {
            unsigned m = atomicAdd(&g_master, 1u) + 1u;
            if (m == (gen + 1u) * NLEAF) {
                __threadfence();
                g_gen = gen + 1u;
            } else {
                while (g_gen == gen) __nanosleep(32);
            }
        } else {
            while (g_gen == gen) __nanosleep(64);
        }
        __threadfence();
    }
    __syncthreads();
}

__global__ void __launch_bounds__(256, 4) decoder_persist(
        const float* __restrict__ enc, const float* __restrict__ yhist,
        const float* __restrict__ attn_w1, const float* __restrict__ attn_w2,
        const float* __restrict__ w_ih,
        const float* __restrict__ fc_w, const float* __restrict__ fc_b,
        const float* __restrict__ fcf_w, const float* __restrict__ fcf_b,
        float* __restrict__ out)
{
    __shared__ Smem sm;
    const int bid = blockIdx.x;
    const int tid = threadIdx.x;
    const int lane = tid & 31, warp = tid >> 5;
    const int b = bid;

    for (int t = 0; t < Tq; t++) {
        // ============ phase 1: step-GEMM partials, one unit per block ============
        if (bid < 256) {
            // gp unit: h @ w_hhT, tile 128x64, K-chunk 64 -> 4 partials
            int kq = bid & 3, tile = bid >> 2;
            int mt = tile >> 4, nt = tile & 15;
            gemm128x64<float>(&sm.a,
                g_h + (size_t)mt * 128 * Dq + kq * 64, Dq,
                g_whhT + (size_t)(kq * 64) * G4 + nt * 64, G4,
                g_gp + (size_t)kq * (Bq * G4) + (size_t)mt * 128 * G4 + nt * 64, G4,
                64, (const float*)0);
        } else {
            // hp unit: [h|c] @ W1_hc, tile 128x64, K-chunk 32 -> 16 partials
            int u = bid - 256;
            int tile = u >> 4, kq = u & 15;
            int mt = tile >> 2, nt = tile & 3;
            const float* A = (kq < 8 ? g_h + kq * 32 : g_c + (kq - 8) * 32)
                             + (size_t)mt * 128 * Dq;
            gemm128x64<float>(&sm.a, A, Dq,
                attn_w1 + (size_t)(kq * 32) * Eq + nt * 64, Eq,
                g_hp + (size_t)kq * (Bq * Eq) + (size_t)mt * 128 * Eq + nt * 64, Eq,
                32, (const float*)0);
        }
        gridbar();

        // ============ phase 2: attention + LSTM, row-local (row b = bid) ============
        {
            float hpv = 0.f;
#pragma unroll
            for (int q = 0; q < 16; q++)
                hpv += __ldcg(&g_hp[(size_t)q * (Bq * Eq) + b * Eq + tid]);
            sm.b.hp[tid] = hpv;
            __syncthreads();
            if (tid < 128) {
                __half2 h2 = __floats2half2_rn(sm.b.hp[2 * tid], sm.b.hp[2 * tid + 1]);
                sm.b.hp2[tid] = *(unsigned*)&h2;
            }
            __syncthreads();

            unsigned hp2r[4];
            float w2r[8];
#pragma unroll
            for (int q = 0; q < 4; q++) hp2r[q] = sm.b.hp2[lane * 4 + q];
#pragma unroll
            for (int j = 0; j < 8; j++) w2r[j] = __ldg(&attn_w2[lane * 8 + j]);

            // scores: 8 warps x 16 t's, 4 loads in flight; tanh in f16x2
            const uint4* preb = (const uint4*)(g_pre + (size_t)b * Tq * Eq);
#pragma unroll
            for (int tb = 0; tb < 4; tb++) {
                int tt0 = warp + tb * 32;
                uint4 pv[4];
#pragma unroll
                for (int j = 0; j < 4; j++)
                    pv[j] = __ldg(preb + (size_t)(tt0 + j * 8) * 32 + lane);
#pragma unroll
                for (int j = 0; j < 4; j++) {
                    const unsigned* ph = (const unsigned*)&pv[j];
                    float a = 0.f;
#pragma unroll
                    for (int q = 0; q < 4; q++) {
                        __half2 x = *(const __half2*)&ph[q] + *(const __half2*)&hp2r[q];
                        unsigned th = tanh_h2(*(unsigned*)&x);
                        float2 f = __half22float2(*(const __half2*)&th);
                        a = fmaf(w2r[2 * q], f.x, a);
                        a = fmaf(w2r[2 * q + 1], f.y, a);
                    }
#pragma unroll
                    for (int o = 16; o; o >>= 1) a += __shfl_xor_sync(0xffffffffu, a, o);
                    if (lane == 0) sm.b.sc[tt0 + j * 8] = a;
                }
            }
            __syncthreads();

            // softmax over T=128 (attn_b2 dropped: shift-invariant)
            float sv = (tid < Tq) ? sm.b.sc[tid] : -3.0e38f;
            float m = sv;
#pragma unroll
            for (int o = 16; o; o >>= 1) m = fmaxf(m, __shfl_xor_sync(0xffffffffu, m, o));
            if (lane == 0) sm.b.red[warp] = m;
            __syncthreads();
            if (tid == 0) {
                float mm = sm.b.red[0];
#pragma unroll
                for (int w = 1; w < 8; w++) mm = fmaxf(mm, sm.b.red[w]);
                sm.b.misc[0] = mm;
            }
            __syncthreads();
            float ex = (tid < Tq) ? __expf(sv - sm.b.misc[0]) : 0.f;
            float ss = ex;
#pragma unroll
            for (int o = 16; o; o >>= 1) ss += __shfl_xor_sync(0xffffffffu, ss, o);
            if (lane == 0) sm.b.red[warp] = ss;
            __syncthreads();
            if (tid == 0) {
                float tot = 0.f;
#pragma unroll
                for (int w = 0; w < 8; w++) tot += sm.b.red[w];
                sm.b.misc[1] = __fdividef(1.0f, tot);
            }
            if (tid < Tq) sm.b.sc[tid] = ex;
            __syncthreads();
            float invs = sm.b.misc[1];

            // y_dot = sum_t ex[t] * encfc[b,t]
            float yd = (tid < Tq) ? sm.b.sc[tid] * __ldg(&g_encfc[b * Tq + tid]) : 0.f;
#pragma unroll
            for (int o = 16; o; o >>= 1) yd += __shfl_xor_sync(0xffffffffu, yd, o);
            if (lane == 0) sm.b.red[warp] = yd;
            __syncthreads();
            if (tid == 0) {
                float tot = 0.f;
#pragma unroll
                for (int w = 0; w < 8; w++) tot += sm.b.red[w];
                sm.b.misc[2] = tot * invs + __ldg(&yhist[b * Tq + t]) * fc_w[256] + fc_b[0];
            }

            // full ctx only at the final step (for fc_final)
            if (t == Tq - 1) {
                float a8[8] = {0.f, 0.f, 0.f, 0.f, 0.f, 0.f, 0.f, 0.f};
                const float4* encb = (const float4*)(enc + (size_t)b * Tq * Eq);
#pragma unroll 2
                for (int i = 0; i < 16; i++) {
                    int tt = (warp << 4) + i;
                    float wgt = sm.b.sc[tt];
                    float4 e0 = __ldg(encb + (size_t)tt * 64 + lane * 2);
                    float4 e1 = __ldg(encb + (size_t)tt * 64 + lane * 2 + 1);
                    a8[0] = fmaf(wgt, e0.x, a8[0]); a8[1] = fmaf(wgt, e0.y, a8[1]);
                    a8[2] = fmaf(wgt, e0.z, a8[2]); a8[3] = fmaf(wgt, e0.w, a8[3]);
                    a8[4] = fmaf(wgt, e1.x, a8[4]); a8[5] = fmaf(wgt, e1.y, a8[5]);
                    a8[6] = fmaf(wgt, e1.z, a8[6]); a8[7] = fmaf(wgt, e1.w, a8[7]);
                }
#pragma unroll
                for (int j = 0; j < 8; j++) sm.b.ctxp[warp][lane * 8 + j] = a8[j];
                __syncthreads();
                float cv = 0.f;
#pragma unroll
                for (int w = 0; w < 8; w++) cv += sm.b.ctxp[w][tid];
                sm.b.ctx[tid] = cv * invs;
            }
            __syncthreads();

            // LSTM epilogue (thread = d)
            float yt = sm.b.misc[2];
            int d = tid;
            float gv[4];
#pragma unroll
            for (int g = 0; g < 4; g++) {
                float a = fmaf(yt, __ldg(&w_ih[g * 256 + d]), g_bsum[g * 256 + d]);
#pragma unroll
                for (int kq = 0; kq < 4; kq++)
                    a += __ldcg(&g_gp[(size_t)kq * (Bq * G4) + (size_t)b * G4 + g * 256 + d]);
                gv[g] = a;
            }
            float cprev = __ldcg(&g_c[b * Dq + d]);
            float cn = sigmoid_f(gv[1]) * cprev + sigmoid_f(gv[0]) * tanhf(gv[2]);
            float hn = sigmoid_f(gv[3]) * tanhf(cn);
            g_c[b * Dq + d] = cn;
            g_h[b * Dq + d] = hn;

            if (t == Tq - 1) {
                float q = hn * __ldg(&fcf_w[d]) + sm.b.ctx[d] * __ldg(&fcf_w[Dq + d]);
#pragma unroll
                for (int o = 16; o; o >>= 1) q += __shfl_xor_sync(0xffffffffu, q, o);
                __syncthreads();
                if (lane == 0) sm.b.red[warp] = q;
                __syncthreads();
                if (tid == 0) {
                    float tot = 0.f;
#pragma unroll
                    for (int w = 0; w < 8; w++) tot += sm.b.red[w];
                    out[b] = tot + fcf_b[0];
                }
            }
        }
        gridbar();
    }
}

__global__ void prep_kernel(const float* __restrict__ w_hh,
                            const float* __restrict__ b_ih,
                            const float* __restrict__ b_hh)
{
    int i = blockIdx.x * blockDim.x + threadIdx.x;
    if (i < G4 * Dq) {
        int j = i >> 8, k = i & 255;
        g_whhT[(size_t)k * G4 + j] = w_hh[i];
    }
    if (i < G4) g_bsum[i] = b_ih[i] + b_hh[i];
    if (i < Bq * Dq) { g_h[i] = 0.f; g_c[i] = 0.f; }
    if (i < NLEAF * 32) g_cnt[i] = 0u;
    if (i == 0) { g_master = 0u; g_gen = 0u; }
}

// encfc[b,t] = enc[b,t,:] . fc_w[0:256]   (one warp per (b,t))
__global__ void __launch_bounds__(256) encfc_kernel(
        const float* __restrict__ enc, const float* __restrict__ fc_w)
{
    int w = blockIdx.x * 8 + (threadIdx.x >> 5);
    int lane = threadIdx.x & 31;
    const float4* p = (const float4*)(enc + (size_t)w * Eq);
    const float4* q = (const float4*)fc_w;
    float s = 0.f;
#pragma unroll
    for (int j = 0; j < 2; j++) {
        float4 e = __ldcg(p + lane + 32 * j);
        float4 f = __ldg(q + lane + 32 * j);
        s += e.x * f.x + e.y * f.y + e.z * f.z + e.w * f.w;
    }
#pragma unroll
    for (int o = 16; o; o >>= 1) s += __shfl_xor_sync(0xffffffffu, s, o);
    if (lane == 0) g_encfc[w] = s;
}

__global__ void __launch_bounds__(256) pre_gemm_kernel(
        const float* __restrict__ enc, const float* __restrict__ attn_w1,
        const float* __restrict__ attn_b1)
{
    __shared__ SmA sa;
    int mt = blockIdx.x >> 2, nt = blockIdx.x & 3;
    gemm128x64<__half>(&sa,
        enc + (size_t)mt * 128 * Eq, Eq,
        attn_w1 + (size_t)(2 * Dq) * Eq + nt * 64, Eq,
        g_pre + (size_t)mt * 128 * Eq + nt * 64, Eq, 256,
        attn_b1 + nt * 64);
}

extern "C" void kernel_launch(void* const* d_in, const int* in_sizes, int n_in,
                              void* d_out, int out_size)
{
    const float* enc     = (const float*)d_in[0];
    const float* yhist   = (const float*)d_in[1];
    const float* attn_w1 = (const float*)d_in[2];
    const float* attn_b1 = (const float*)d_in[3];
    const float* attn_w2 = (const float*)d_in[4];
    // d_in[5] = attn_b2: unused (softmax is shift-invariant)
    const float* w_ih    = (const float*)d_in[6];
    const float* w_hh    = (const float*)d_in[7];
    const float* b_ih    = (const float*)d_in[8];
    const float* b_hh    = (const float*)d_in[9];
    const float* fc_w    = (const float*)d_in[10];
    const float* fc_b    = (const float*)d_in[11];
    const float* fcf_w   = (const float*)d_in[12];
    const float* fcf_b   = (const float*)d_in[13];
    float* out = (float*)d_out;

    prep_kernel<<<1024, 256>>>(w_hh, b_ih, b_hh);
    encfc_kernel<<<BT / 8, 256>>>(enc, fc_w);
    pre_gemm_kernel<<<2048, 256>>>(enc, attn_w1, attn_b1);
    decoder_persist<<<NBLK, 256>>>(enc, yhist, attn_w1, attn_w2, w_ih,
                                   fc_w, fc_b, fcf_w, fcf_b, out);
}